// round 16
// baseline (speedup 1.0000x reference)
#include <cuda_runtime.h>
#include <cuda_bf16.h>

#define B_ 128
#define T_ 512
#define E_ 256
#define U_ 256

#define CH 36                // padded floats per 32-float h chunk (144B)
#define HB (8 * CH)          // 288 floats per (buf,batch)

typedef unsigned long long u64t;

// 64MB scratch: xw[t][b][u]
__device__ __align__(16) float g_xw[T_ * B_ * U_];

__device__ __forceinline__ u64t ffma2(u64t a, u64t b, u64t c) {
    u64t d;
    asm("fma.rn.f32x2 %0, %1, %2, %3;" : "=l"(d) : "l"(a), "l"(b), "l"(c));
    return d;
}
__device__ __forceinline__ float f2lo(u64t v) { return __uint_as_float((unsigned)(v & 0xffffffffull)); }
__device__ __forceinline__ float f2hi(u64t v) { return __uint_as_float((unsigned)(v >> 32)); }
__device__ __forceinline__ float tanh_fast(float x) {
    float ex = __expf(2.0f * x);
    return 1.0f - __fdividef(2.0f, ex + 1.0f);
}

// ---------------- mbarrier / cluster helpers (R4/R14 verbatim) ----------------
__device__ __forceinline__ void mbar_init(unsigned addr, unsigned cnt) {
    asm volatile("mbarrier.init.shared.b64 [%0], %1;" :: "r"(addr), "r"(cnt) : "memory");
}
__device__ __forceinline__ void mbar_expect(unsigned addr, unsigned bytes) {
    asm volatile("mbarrier.arrive.expect_tx.shared.b64 _, [%0], %1;"
                 :: "r"(addr), "r"(bytes) : "memory");
}
__device__ __forceinline__ void mbar_wait(unsigned addr, unsigned parity) {
    unsigned done;
    asm volatile(
        "{\n\t.reg .pred p;\n\t"
        "mbarrier.try_wait.parity.acquire.cta.shared::cta.b64 p, [%1], %2;\n\t"
        "selp.b32 %0, 1, 0, p;\n\t}"
        : "=r"(done) : "r"(addr), "r"(parity) : "memory");
    if (!done) {
        asm volatile(
            "{\n\t.reg .pred P1;\n\t"
            "W_%=:\n\t"
            "mbarrier.try_wait.parity.acquire.cta.shared::cta.b64 P1, [%0], %1, 0x989680;\n\t"
            "@P1 bra D_%=;\n\t"
            "bra W_%=;\n\t"
            "D_%=:\n\t}"
            :: "r"(addr), "r"(parity) : "memory");
    }
}
__device__ __forceinline__ void st_async_f32(unsigned raddr, float v, unsigned rbar) {
    asm volatile("st.async.shared::cluster.mbarrier::complete_tx::bytes.b32 [%0], %1, [%2];"
                 :: "r"(raddr), "r"(__float_as_uint(v)), "r"(rbar) : "memory");
}
__device__ __forceinline__ void cluster_sync_() {
    asm volatile("barrier.cluster.arrive.aligned;" ::: "memory");
    asm volatile("barrier.cluster.wait.aligned;" ::: "memory");
}

// ---------------------------------------------------------------------------
// Phase 1: xw[t][b][u] = sum_e emb[sentence[b][t]][e] * W[u][e]  (unchanged)
// ---------------------------------------------------------------------------
__global__ void __launch_bounds__(256)
xw_kernel(const int* __restrict__ sent, const float* __restrict__ emb,
          const float* __restrict__ Wm)
{
    __shared__ __align__(16) float2 As2[16 * 64];
    __shared__ __align__(16) float  Bs[16 * 256];
    __shared__ int idx[64];

    const int tid = threadIdx.x;
    const int r0 = blockIdx.x * 64;
    const int t  = r0 >> 7;
    const int b0 = r0 & 127;

    if (tid < 64) idx[tid] = sent[(b0 + tid) * T_ + t];
    __syncthreads();

    const int tx = tid & 15;
    const int ty = tid >> 4;
    const int arow = tid >> 2;
    const int aq = tid & 3;

    u64t acc[4][8];
    #pragma unroll
    for (int i = 0; i < 4; i++)
        #pragma unroll
        for (int p = 0; p < 8; p++) acc[i][p] = 0ull;

    float4 va = *(const float4*)(emb + (size_t)idx[arow] * E_ + aq * 4);
    float4 vb0 = *(const float4*)(Wm + (size_t)tid * E_ + 0);
    float4 vb1 = *(const float4*)(Wm + (size_t)tid * E_ + 4);
    float4 vb2 = *(const float4*)(Wm + (size_t)tid * E_ + 8);
    float4 vb3 = *(const float4*)(Wm + (size_t)tid * E_ + 12);

    for (int ko = 0; ko < 16; ko++) {
        if (ko > 0) __syncthreads();

        As2[(aq * 4 + 0) * 64 + arow] = make_float2(va.x, va.x);
        As2[(aq * 4 + 1) * 64 + arow] = make_float2(va.y, va.y);
        As2[(aq * 4 + 2) * 64 + arow] = make_float2(va.z, va.z);
        As2[(aq * 4 + 3) * 64 + arow] = make_float2(va.w, va.w);
        {
            const float v[16] = {vb0.x, vb0.y, vb0.z, vb0.w, vb1.x, vb1.y, vb1.z, vb1.w,
                                 vb2.x, vb2.y, vb2.z, vb2.w, vb3.x, vb3.y, vb3.z, vb3.w};
            #pragma unroll
            for (int j = 0; j < 16; j++) Bs[j * 256 + tid] = v[j];
        }
        __syncthreads();

        if (ko < 15) {
            const int kb = (ko + 1) * 16;
            va  = *(const float4*)(emb + (size_t)idx[arow] * E_ + kb + aq * 4);
            vb0 = *(const float4*)(Wm + (size_t)tid * E_ + kb + 0);
            vb1 = *(const float4*)(Wm + (size_t)tid * E_ + kb + 4);
            vb2 = *(const float4*)(Wm + (size_t)tid * E_ + kb + 8);
            vb3 = *(const float4*)(Wm + (size_t)tid * E_ + kb + 12);
        }

        #pragma unroll
        for (int k = 0; k < 16; k++) {
            u64t ap[4];
            #pragma unroll
            for (int i = 0; i < 4; i++)
                ap[i] = *(const u64t*)&As2[k * 64 + ty * 4 + i];
            #pragma unroll
            for (int q = 0; q < 4; q++) {
                const ulonglong2 bq = *(const ulonglong2*)&Bs[k * 256 + q * 64 + tx * 4];
                #pragma unroll
                for (int i = 0; i < 4; i++) {
                    acc[i][2 * q + 0] = ffma2(bq.x, ap[i], acc[i][2 * q + 0]);
                    acc[i][2 * q + 1] = ffma2(bq.y, ap[i], acc[i][2 * q + 1]);
                }
            }
        }
    }

    #pragma unroll
    for (int i = 0; i < 4; i++) {
        const int rg = r0 + ty * 4 + i;
        #pragma unroll
        for (int q = 0; q < 4; q++) {
            float4 o;
            o.x = f2lo(acc[i][2 * q + 0]); o.y = f2hi(acc[i][2 * q + 0]);
            o.z = f2lo(acc[i][2 * q + 1]); o.w = f2hi(acc[i][2 * q + 1]);
            __stcs((float4*)(g_xw + (size_t)rg * U_ + q * 64 + tx * 4), o);
        }
    }
}

// ---------------------------------------------------------------------------
// Phase 2: recurrence — R15 verbatim except ONE change: h chunks interleave
// local/peer halves (slot(u) = ((u&127)>>4)*36 + (u>>7)*16 + (u&15)) and the
// step computes the local-half dot BEFORE the mbar wait, peer-half after,
// hiding the ~90-cyc TRYWAIT fast-path + CTA skew behind compute.
// Safety: local-half reads precede our sends, and the peer's next-phase
// writes to this buffer cannot precede our sends (distance-2 handshake).
// ---------------------------------------------------------------------------
__global__ void __cluster_dims__(2, 1, 1) __launch_bounds__(256, 1)
rnn_kernel(const float* __restrict__ Um,
           const float* __restrict__ W1, const float* __restrict__ b1v,
           const float* __restrict__ W2, const float* __restrict__ b2v,
           float* __restrict__ outp)
{
    __shared__ __align__(16) float hbuf[2][2][HB];      // [buf][b][interleaved]
    __shared__ __align__(8)  unsigned long long fullbar[2];
    __shared__ float hid[2][32];

    const int tid = threadIdx.x;
    unsigned rank;
    asm("mov.u32 %0, %%cluster_ctarank;" : "=r"(rank));
    const unsigned peer = rank ^ 1u;
    const int b0 = (blockIdx.x >> 1) * 2;
    const int uhalf = (int)rank * 128;
    const int phalf = (int)peer * 128;
    const int uu = tid >> 3;             // 0..31 -> 4 rows each
    const int ju = tid & 7;              // chunk index

    // U rows uhalf+uu*4+a; cols split: local j = uhalf+ju*16..+15,
    // peer j = phalf+ju*16..+15  -> Ur_l[4][8] + Ur_p[4][8] (64 u64 total)
    u64t Ur_l[4][8], Ur_p[4][8];
    #pragma unroll
    for (int a = 0; a < 4; a++) {
        const float* rowp = Um + (size_t)(uhalf + uu * 4 + a) * U_;
        const u64t* pl = (const u64t*)(rowp + uhalf + ju * 16);
        const u64t* pp = (const u64t*)(rowp + phalf + ju * 16);
        #pragma unroll
        for (int q = 0; q < 8; q++) { Ur_l[a][q] = pl[q]; Ur_p[a][q] = pp[q]; }
    }

    for (int i = tid; i < 2 * 2 * HB; i += 256) ((float*)hbuf)[i] = 0.0f;

    const unsigned lh = (unsigned)__cvta_generic_to_shared(hbuf);
    const unsigned lb = (unsigned)__cvta_generic_to_shared(fullbar);
    unsigned rh, rb_;
    asm("mapa.shared::cluster.u32 %0, %1, %2;" : "=r"(rh)  : "r"(lh), "r"(peer));
    asm("mapa.shared::cluster.u32 %0, %1, %2;" : "=r"(rb_) : "r"(lb), "r"(peer));

    if (tid == 0) {
        mbar_init(lb + 0, 1);
        mbar_init(lb + 8, 1);
        mbar_expect(lb + 8, 1024);   // arm full[1] for phase 0 (peer's t=0 txs)
    }
    __syncthreads();
    cluster_sync_();                 // peer's init visible before any st.async

    // finalize role: batch = ju>>2, row = uhalf + uu*4 + (ju&3)
    const int batch = ju >> 2;
    const int u_fin = uhalf + uu * 4 + (ju & 3);
    // interleaved slot of u_fin (u_fin is in OUR half -> +rank*16)
    const int po = ((u_fin & 127) >> 4) * CH + (int)rank * 16 + (u_fin & 15);
    unsigned ph0 = 0, ph1 = 0;

    float cxw = __ldcs(g_xw + (size_t)(b0 + batch) * U_ + u_fin);
    float hval = 0.0f;

    for (int t = 0; t < T_; t++) {
        const int rbuf = t & 1;
        const int wbuf = rbuf ^ 1;

        // prefetch next step's xw (consumed next iteration)
        const int tn = (t + 1 < T_) ? t + 1 : t;
        const float nxw = __ldcs(g_xw + (size_t)tn * (B_ * U_) +
                                 (size_t)(b0 + batch) * U_ + u_fin);

        // ---- local-half dot (no peer dependency) ----
        u64t acc[8];
        #pragma unroll
        for (int i = 0; i < 8; i++) acc[i] = 0ull;
        #pragma unroll
        for (int B2 = 0; B2 < 2; B2++) {
            u64t hl[8];
            const u64t* hp = (const u64t*)&hbuf[rbuf][B2][ju * CH + (int)rank * 16];
            #pragma unroll
            for (int q = 0; q < 8; q++) hl[q] = hp[q];
            #pragma unroll
            for (int a = 0; a < 4; a++) {
                u64t ac = acc[B2 * 4 + a];
                #pragma unroll
                for (int q = 0; q < 8; q++) ac = ffma2(Ur_l[a][q], hl[q], ac);
                acc[B2 * 4 + a] = ac;
            }
        }

        // ---- wait for peer txs (hidden behind the local dot) ----
        if (t > 0) {
            if (rbuf == 0) { mbar_wait(lb + 0, ph0); ph0 ^= 1u; }
            else           { mbar_wait(lb + 8, ph1); ph1 ^= 1u; }
        }
        if (tid == 0) mbar_expect(lb + rbuf * 8, 1024);  // re-arm for next phase

        // ---- peer-half dot ----
        #pragma unroll
        for (int B2 = 0; B2 < 2; B2++) {
            u64t hp2[8];
            const u64t* hq = (const u64t*)&hbuf[rbuf][B2][ju * CH + (int)peer * 16];
            #pragma unroll
            for (int q = 0; q < 8; q++) hp2[q] = hq[q];
            #pragma unroll
            for (int a = 0; a < 4; a++) {
                u64t ac = acc[B2 * 4 + a];
                #pragma unroll
                for (int q = 0; q < 8; q++) ac = ffma2(Ur_p[a][q], hp2[q], ac);
                acc[B2 * 4 + a] = ac;
            }
        }

        float v[8];
        #pragma unroll
        for (int i = 0; i < 8; i++) v[i] = f2lo(acc[i]) + f2hi(acc[i]);

        // reduce-scatter 8 values over 8 lanes (xor 4,2,1): lane ju -> v[ju]
        float w[4];
        {
            const bool hi = (ju & 4) != 0;
            #pragma unroll
            for (int a = 0; a < 4; a++) {
                const float keep = hi ? v[a + 4] : v[a];
                const float send = hi ? v[a] : v[a + 4];
                w[a] = keep + __shfl_xor_sync(0xffffffffu, send, 4);
            }
        }
        float x[2];
        {
            const bool hi = (ju & 2) != 0;
            #pragma unroll
            for (int a = 0; a < 2; a++) {
                const float keep = hi ? w[a + 2] : w[a];
                const float send = hi ? w[a] : w[a + 2];
                x[a] = keep + __shfl_xor_sync(0xffffffffu, send, 2);
            }
        }
        float d;
        {
            const bool hi = (ju & 1) != 0;
            const float keep = hi ? x[1] : x[0];
            const float send = hi ? x[0] : x[1];
            d = keep + __shfl_xor_sync(0xffffffffu, send, 1);
        }

        hval = tanh_fast(d + cxw);
        const unsigned off = (unsigned)((wbuf * 2 + batch) * HB + po);
        hbuf[wbuf][batch][po] = hval;
        st_async_f32(rh + off * 4u, hval, rb_ + (unsigned)wbuf * 8u);

        __syncthreads();   // local-half visibility for next step's reads
        cxw = nxw;
    }

    // Final h is in buf 0; wait for peer's last txs, then local barrier.
    mbar_wait(lb + 0, ph0);
    __syncthreads();

    if (rank == 0) {
        if (tid < 32) {
            for (int bi = 0; bi < 2; bi++) {
                float acc = b1v[tid];
                const float* hr = hbuf[0][bi];
                #pragma unroll 8
                for (int j = 0; j < 256; j++)
                    acc = fmaf(hr[((j & 127) >> 4) * CH + ((j >> 7) << 4) + (j & 15)],
                               __ldg(W1 + j * 32 + tid), acc);
                hid[bi][tid] = fmaxf(acc, 0.0f);
            }
        }
        __syncthreads();
        if (tid < 2) {
            float l0 = b2v[0], l1 = b2v[1];
            #pragma unroll
            for (int k = 0; k < 32; k++) {
                const float hv2 = hid[tid][k];
                l0 = fmaf(hv2, __ldg(W2 + k * 2 + 0), l0);
                l1 = fmaf(hv2, __ldg(W2 + k * 2 + 1), l1);
            }
            const float m = fmaxf(l0, l1);
            const float e0 = expf(l0 - m);
            const float e1 = expf(l1 - m);
            const float inv = 1.0f / (e0 + e1);
            outp[(b0 + tid) * 2 + 0] = e0 * inv;
            outp[(b0 + tid) * 2 + 1] = e1 * inv;
        }
    }
    cluster_sync_();   // no CTA exits while peer traffic could be in flight
}

// ---------------------------------------------------------------------------
extern "C" void kernel_launch(void* const* d_in, const int* in_sizes, int n_in,
                              void* d_out, int out_size)
{
    const int*   sent = (const int*)d_in[0];
    const float* emb  = (const float*)d_in[1];
    const float* Wm   = (const float*)d_in[2];
    const float* Um   = (const float*)d_in[3];
    const float* W1   = (const float*)d_in[4];
    const float* b1v  = (const float*)d_in[5];
    const float* W2   = (const float*)d_in[6];
    const float* b2v  = (const float*)d_in[7];
    float* outp = (float*)d_out;
    (void)in_sizes; (void)n_in; (void)out_size;

    xw_kernel<<<1024, 256>>>(sent, emb, Wm);
    rnn_kernel<<<128, 256>>>(Um, W1, b1v, W2, b2v, outp);
}